// round 1
// baseline (speedup 1.0000x reference)
#include <cuda_runtime.h>
#include <math.h>

// Problem dims (fixed by reference setup_inputs)
#define BB   4
#define LL   4096
#define MM   (BB*LL)      // 16384 rows
#define DD   512
#define FF   2048
#define NITER 11
#define THRESH (1.0f - 0.01f)

// Scratch (device globals; no allocation allowed)
__device__ float g_st[(size_t)MM * DD];     // carry state (32 MB)
__device__ float g_hmid[(size_t)MM * FF];   // FFN hidden (128 MB)
__device__ float g_hp[MM];                  // halting probability
__device__ float g_uw[MM];                  // update weights per row
__device__ int   g_flag[NITER + 1];         // "any position active entering step t"

// ---------------------------------------------------------------------------
// Init: zero outputs/state, copy carry, set flags
// ---------------------------------------------------------------------------
__global__ void init_kernel(const float* __restrict__ state, float* __restrict__ out)
{
    size_t i = (size_t)blockIdx.x * blockDim.x + threadIdx.x;
    if (i < (size_t)MM * DD) {
        g_st[i] = state[i];
        out[i] = 0.0f;                       // new_state accumulator
    }
    if (i < MM) {
        g_hp[i] = 0.0f;
        out[(size_t)MM * DD + i] = 0.0f;          // n_updates
        out[(size_t)MM * DD + MM + i] = 0.0f;     // remainders
    }
    if (i <= NITER) g_flag[i] = (i == 0) ? 1 : 0;
}

// ---------------------------------------------------------------------------
// Ponder: one warp per row. s = st + emb[t]; p = sigmoid(s.Wp + bp);
// halting state machine; uw; sets g_flag[t+1] if anyone still active.
// ---------------------------------------------------------------------------
__global__ void ponder_kernel(const float* __restrict__ step_emb,
                              const float* __restrict__ Wp,
                              const float* __restrict__ bp,
                              float* __restrict__ out_nup,
                              float* __restrict__ out_rem,
                              int t)
{
    if (!g_flag[t]) return;
    int row  = blockIdx.x * 8 + (threadIdx.x >> 5);
    int lane = threadIdx.x & 31;

    const float4* st4 = (const float4*)(g_st + (size_t)row * DD);
    const float4* e4  = (const float4*)(step_emb + (size_t)t * DD);
    const float4* w4  = (const float4*)Wp;

    float dot = 0.0f;
    #pragma unroll
    for (int i = lane; i < DD / 4; i += 32) {
        float4 s = st4[i], e = e4[i], w = w4[i];
        dot += (s.x + e.x) * w.x + (s.y + e.y) * w.y
             + (s.z + e.z) * w.z + (s.w + e.w) * w.w;
    }
    #pragma unroll
    for (int o = 16; o; o >>= 1) dot += __shfl_xor_sync(0xffffffffu, dot, o);

    __shared__ int s_active;
    if (threadIdx.x == 0) s_active = 0;
    __syncthreads();

    if (lane == 0) {
        float p = 1.0f / (1.0f + expf(-(dot + bp[0])));
        float hp = g_hp[row];
        float still0 = (hp < 1.0f) ? 1.0f : 0.0f;
        float q  = hp + p * still0;
        float nh = (q >  THRESH) ? still0 : 0.0f;   // new_halted
        float st = (q <= THRESH) ? still0 : 0.0f;   // still
        hp = hp + p * st;
        float rem = out_rem[row] + nh * (1.0f - hp);
        hp = hp + nh * rem;
        out_nup[row] += st + nh;
        g_hp[row]   = hp;
        out_rem[row] = rem;
        g_uw[row]   = p * st + nh * rem;
        if (hp < 1.0f) atomicOr(&s_active, 1);
    }
    __syncthreads();
    if (threadIdx.x == 0 && s_active) atomicOr(&g_flag[t + 1], 1);
}

// ---------------------------------------------------------------------------
// GEMM1: hmid[M,F] = relu( (st + emb[t]) @ W1 + b1 )
// 128x128x16 tile, 256 threads, 8x8 per thread, reg prefetch
// ---------------------------------------------------------------------------
#define BK 16

__global__ __launch_bounds__(256, 2) void gemm1_kernel(
    const float* __restrict__ W1, const float* __restrict__ b1,
    const float* __restrict__ step_emb, int t)
{
    if (!g_flag[t]) return;
    __shared__ float As[BK][132];
    __shared__ float Bs[BK][132];

    const int tid = threadIdx.x;
    const int tx = tid & 15;
    const int ty = tid >> 4;
    const int bm = blockIdx.y * 128;
    const int bn = blockIdx.x * 128;
    const float* __restrict__ emb = step_emb + (size_t)t * DD;

    const int am = tid >> 2;            // 0..63 (rows am, am+64)
    const int ak = (tid & 3) * 4;       // k offset within tile
    const int bk = tid >> 5;            // 0..7 (rows bk, bk+8)
    const int bo = (tid & 31) * 4;      // n offset within tile

    float4 a0, a1, c0, c1;
    {
        const float* Ap = g_st + (size_t)(bm + am) * DD + ak;
        a0 = *(const float4*)Ap;
        a1 = *(const float4*)(Ap + (size_t)64 * DD);
        float4 e = *(const float4*)(emb + ak);
        a0.x += e.x; a0.y += e.y; a0.z += e.z; a0.w += e.w;
        a1.x += e.x; a1.y += e.y; a1.z += e.z; a1.w += e.w;
        const float* Bp = W1 + (size_t)bk * FF + bn + bo;
        c0 = *(const float4*)Bp;
        c1 = *(const float4*)(Bp + (size_t)8 * FF);
    }

    float acc[8][8] = {};
    const int KT = DD / BK;  // 32

    for (int kt = 0; kt < KT; ++kt) {
        As[ak + 0][am] = a0.x; As[ak + 1][am] = a0.y;
        As[ak + 2][am] = a0.z; As[ak + 3][am] = a0.w;
        As[ak + 0][am + 64] = a1.x; As[ak + 1][am + 64] = a1.y;
        As[ak + 2][am + 64] = a1.z; As[ak + 3][am + 64] = a1.w;
        *(float4*)&Bs[bk][bo]     = c0;
        *(float4*)&Bs[bk + 8][bo] = c1;
        __syncthreads();

        if (kt + 1 < KT) {
            int k0 = (kt + 1) * BK;
            const float* Ap = g_st + (size_t)(bm + am) * DD + k0 + ak;
            a0 = *(const float4*)Ap;
            a1 = *(const float4*)(Ap + (size_t)64 * DD);
            float4 e = *(const float4*)(emb + k0 + ak);
            a0.x += e.x; a0.y += e.y; a0.z += e.z; a0.w += e.w;
            a1.x += e.x; a1.y += e.y; a1.z += e.z; a1.w += e.w;
            const float* Bp = W1 + (size_t)(k0 + bk) * FF + bn + bo;
            c0 = *(const float4*)Bp;
            c1 = *(const float4*)(Bp + (size_t)8 * FF);
        }

        #pragma unroll
        for (int k = 0; k < BK; ++k) {
            float4 fa0 = *(const float4*)&As[k][ty * 4];
            float4 fa1 = *(const float4*)&As[k][64 + ty * 4];
            float4 fb0 = *(const float4*)&Bs[k][tx * 4];
            float4 fb1 = *(const float4*)&Bs[k][64 + tx * 4];
            float a[8] = {fa0.x, fa0.y, fa0.z, fa0.w, fa1.x, fa1.y, fa1.z, fa1.w};
            float b[8] = {fb0.x, fb0.y, fb0.z, fb0.w, fb1.x, fb1.y, fb1.z, fb1.w};
            #pragma unroll
            for (int i = 0; i < 8; ++i)
                #pragma unroll
                for (int j = 0; j < 8; ++j)
                    acc[i][j] += a[i] * b[j];
        }
        __syncthreads();
    }

    #pragma unroll
    for (int i = 0; i < 8; ++i) {
        int m = bm + ((i < 4) ? (ty * 4 + i) : (64 + ty * 4 + i - 4));
        float* outp = g_hmid + (size_t)m * FF + bn;
        #pragma unroll
        for (int jj = 0; jj < 2; ++jj) {
            int cc = jj * 64 + tx * 4;
            float4 v;
            v.x = fmaxf(acc[i][jj * 4 + 0] + b1[bn + cc + 0], 0.0f);
            v.y = fmaxf(acc[i][jj * 4 + 1] + b1[bn + cc + 1], 0.0f);
            v.z = fmaxf(acc[i][jj * 4 + 2] + b1[bn + cc + 2], 0.0f);
            v.w = fmaxf(acc[i][jj * 4 + 3] + b1[bn + cc + 3], 0.0f);
            *(float4*)(outp + cc) = v;
        }
    }
}

// ---------------------------------------------------------------------------
// GEMM2: h[M,D] = hmid @ W2 + b2, masked; prev += h*uw; carry st = h
// ---------------------------------------------------------------------------
__global__ __launch_bounds__(256, 2) void gemm2_kernel(
    const float* __restrict__ W2, const float* __restrict__ b2,
    const float* __restrict__ mask, float* __restrict__ out_prev, int t)
{
    if (!g_flag[t]) return;
    __shared__ float As[BK][132];
    __shared__ float Bs[BK][132];

    const int tid = threadIdx.x;
    const int tx = tid & 15;
    const int ty = tid >> 4;
    const int bm = blockIdx.y * 128;
    const int bn = blockIdx.x * 128;

    const int am = tid >> 2;
    const int ak = (tid & 3) * 4;
    const int bk = tid >> 5;
    const int bo = (tid & 31) * 4;

    float4 a0, a1, c0, c1;
    {
        const float* Ap = g_hmid + (size_t)(bm + am) * FF + ak;
        a0 = *(const float4*)Ap;
        a1 = *(const float4*)(Ap + (size_t)64 * FF);
        const float* Bp = W2 + (size_t)bk * DD + bn + bo;
        c0 = *(const float4*)Bp;
        c1 = *(const float4*)(Bp + (size_t)8 * DD);
    }

    float acc[8][8] = {};
    const int KT = FF / BK;  // 128

    for (int kt = 0; kt < KT; ++kt) {
        As[ak + 0][am] = a0.x; As[ak + 1][am] = a0.y;
        As[ak + 2][am] = a0.z; As[ak + 3][am] = a0.w;
        As[ak + 0][am + 64] = a1.x; As[ak + 1][am + 64] = a1.y;
        As[ak + 2][am + 64] = a1.z; As[ak + 3][am + 64] = a1.w;
        *(float4*)&Bs[bk][bo]     = c0;
        *(float4*)&Bs[bk + 8][bo] = c1;
        __syncthreads();

        if (kt + 1 < KT) {
            int k0 = (kt + 1) * BK;
            const float* Ap = g_hmid + (size_t)(bm + am) * FF + k0 + ak;
            a0 = *(const float4*)Ap;
            a1 = *(const float4*)(Ap + (size_t)64 * FF);
            const float* Bp = W2 + (size_t)(k0 + bk) * DD + bn + bo;
            c0 = *(const float4*)Bp;
            c1 = *(const float4*)(Bp + (size_t)8 * DD);
        }

        #pragma unroll
        for (int k = 0; k < BK; ++k) {
            float4 fa0 = *(const float4*)&As[k][ty * 4];
            float4 fa1 = *(const float4*)&As[k][64 + ty * 4];
            float4 fb0 = *(const float4*)&Bs[k][tx * 4];
            float4 fb1 = *(const float4*)&Bs[k][64 + tx * 4];
            float a[8] = {fa0.x, fa0.y, fa0.z, fa0.w, fa1.x, fa1.y, fa1.z, fa1.w};
            float b[8] = {fb0.x, fb0.y, fb0.z, fb0.w, fb1.x, fb1.y, fb1.z, fb1.w};
            #pragma unroll
            for (int i = 0; i < 8; ++i)
                #pragma unroll
                for (int j = 0; j < 8; ++j)
                    acc[i][j] += a[i] * b[j];
        }
        __syncthreads();
    }

    #pragma unroll
    for (int i = 0; i < 8; ++i) {
        int m = bm + ((i < 4) ? (ty * 4 + i) : (64 + ty * 4 + i - 4));
        float mk  = mask[m];
        float uwv = g_uw[m];
        float* pp = out_prev + (size_t)m * DD + bn;
        float* sp = g_st     + (size_t)m * DD + bn;
        #pragma unroll
        for (int jj = 0; jj < 2; ++jj) {
            int cc = jj * 64 + tx * 4;
            float4 h;
            h.x = (acc[i][jj * 4 + 0] + b2[bn + cc + 0]) * mk;
            h.y = (acc[i][jj * 4 + 1] + b2[bn + cc + 1]) * mk;
            h.z = (acc[i][jj * 4 + 2] + b2[bn + cc + 2]) * mk;
            h.w = (acc[i][jj * 4 + 3] + b2[bn + cc + 3]) * mk;
            float4 pv = *(const float4*)(pp + cc);
            pv.x += h.x * uwv; pv.y += h.y * uwv;
            pv.z += h.z * uwv; pv.w += h.w * uwv;
            *(float4*)(pp + cc) = pv;
            *(float4*)(sp + cc) = h;
        }
    }
}

// ---------------------------------------------------------------------------
extern "C" void kernel_launch(void* const* d_in, const int* in_sizes, int n_in,
                              void* d_out, int out_size)
{
    const float* state    = (const float*)d_in[0];
    const float* mask     = (const float*)d_in[1];
    const float* step_emb = (const float*)d_in[2];
    const float* Wp       = (const float*)d_in[3];
    const float* bp       = (const float*)d_in[4];
    const float* W1       = (const float*)d_in[5];
    const float* b1       = (const float*)d_in[6];
    const float* W2       = (const float*)d_in[7];
    const float* b2       = (const float*)d_in[8];

    float* out      = (float*)d_out;
    float* out_nup  = out + (size_t)MM * DD;
    float* out_rem  = out_nup + MM;

    init_kernel<<<(MM * DD + 255) / 256, 256>>>(state, out);

    dim3 g1(FF / 128, MM / 128);   // (16, 128)
    dim3 g2(DD / 128, MM / 128);   // (4, 128)
    for (int t = 0; t < NITER; ++t) {
        ponder_kernel<<<MM / 8, 256>>>(step_emb, Wp, bp, out_nup, out_rem, t);
        gemm1_kernel<<<g1, 256>>>(W1, b1, step_emb, t);
        gemm2_kernel<<<g2, 256>>>(W2, b2, mask, out, t);
    }
}

// round 2
// speedup vs baseline: 1.3797x; 1.3797x over previous
#include <cuda_runtime.h>
#include <math.h>

#define MM   16384        // B*L rows
#define DD   512
#define FF   2048
#define NITER 11
#define THRESH (1.0f - 0.01f)
#define BK 16

// Scratch (device globals; allocation is forbidden)
__device__ float g_st[(size_t)MM * DD];     // carried state (original row order)
__device__ float g_s [(size_t)MM * DD];     // compacted s = st + emb[t]
__device__ float g_hmid[(size_t)MM * FF];   // compacted FFN hidden
__device__ float g_hp[MM];
__device__ float g_uw[MM];
__device__ int   g_idx[MM];                 // compact -> original row
__device__ int   g_nact[NITER + 1];         // active count entering step t
__device__ int   g_flag[NITER + 1];

// ---------------------------------------------------------------------------
__device__ __forceinline__ void cp_async16(void* smem, const void* gmem)
{
    unsigned s = (unsigned)__cvta_generic_to_shared(smem);
    asm volatile("cp.async.cg.shared.global [%0], [%1], 16;\n" :: "r"(s), "l"(gmem));
}

// ---------------------------------------------------------------------------
__global__ void init_kernel(const float* __restrict__ state, float* __restrict__ out)
{
    size_t i = (size_t)blockIdx.x * blockDim.x + threadIdx.x;
    if (i < (size_t)MM * DD) {
        g_st[i] = state[i];
        out[i]  = 0.0f;
    }
    if (i < MM) {
        g_hp[i] = 0.0f;
        out[(size_t)MM * DD + i] = 0.0f;        // n_updates
        out[(size_t)MM * DD + MM + i] = 0.0f;   // remainders
    }
    if (i <= NITER) { g_flag[i] = (i == 0) ? 1 : 0; g_nact[i] = 0; }
}

// ---------------------------------------------------------------------------
// Ponder: one warp per row; skips halted rows; builds compact active list.
// Math kept bit-identical to the passing R1 version.
// ---------------------------------------------------------------------------
__global__ void ponder_kernel(const float* __restrict__ step_emb,
                              const float* __restrict__ Wp,
                              const float* __restrict__ bp,
                              float* __restrict__ out_nup,
                              float* __restrict__ out_rem,
                              int t)
{
    if (!g_flag[t]) return;
    int row  = blockIdx.x * 8 + (threadIdx.x >> 5);
    int lane = threadIdx.x & 31;

    __shared__ int s_active;
    if (threadIdx.x == 0) s_active = 0;
    __syncthreads();

    float hp = g_hp[row];
    if (hp < 1.0f) {
        const float4* st4 = (const float4*)(g_st + (size_t)row * DD);
        const float4* e4  = (const float4*)(step_emb + (size_t)t * DD);
        const float4* w4  = (const float4*)Wp;

        float dot = 0.0f;
        #pragma unroll
        for (int i = lane; i < DD / 4; i += 32) {
            float4 s = st4[i], e = e4[i], w = w4[i];
            dot += (s.x + e.x) * w.x + (s.y + e.y) * w.y
                 + (s.z + e.z) * w.z + (s.w + e.w) * w.w;
        }
        #pragma unroll
        for (int o = 16; o; o >>= 1) dot += __shfl_xor_sync(0xffffffffu, dot, o);

        if (lane == 0) {
            float p = 1.0f / (1.0f + expf(-(dot + bp[0])));
            float q  = hp + p;
            float nh = (q >  THRESH) ? 1.0f : 0.0f;
            float st = (q <= THRESH) ? 1.0f : 0.0f;
            hp = hp + p * st;
            float rem = out_rem[row] + nh * (1.0f - hp);
            hp = hp + nh * rem;
            out_nup[row] += 1.0f;                 // still + new_halted == 1 here
            g_hp[row]    = hp;
            out_rem[row] = rem;
            g_uw[row]    = p * st + nh * rem;
            int pos = atomicAdd(&g_nact[t], 1);
            g_idx[pos] = row;
            if (hp < 1.0f) atomicOr(&s_active, 1);
        }
    }
    __syncthreads();
    if (threadIdx.x == 0 && s_active) atomicOr(&g_flag[t + 1], 1);
}

// ---------------------------------------------------------------------------
// Prep: gather active rows into dense g_s = st[idx] + emb[t]
// ---------------------------------------------------------------------------
__global__ void prep_kernel(const float* __restrict__ step_emb, int t)
{
    int nact = g_nact[t];
    int gid = blockIdx.x * blockDim.x + threadIdx.x;
    int r = gid >> 7;                 // 128 float4 per row
    if (r >= nact) return;
    int c = (gid & 127) << 2;
    int row = g_idx[r];
    float4 s = *(const float4*)(g_st + (size_t)row * DD + c);
    float4 e = *(const float4*)(step_emb + (size_t)t * DD + c);
    s.x += e.x; s.y += e.y; s.z += e.z; s.w += e.w;
    *(float4*)(g_s + (size_t)r * DD + c) = s;
}

// ---------------------------------------------------------------------------
// GEMM core: 128x128x16, 256 thr, 8x8/thr, cp.async double-buffered smem.
// MODE 0: hmid = relu(g_s @ W1 + b1)          (dense in, dense out)
// MODE 1: h = hmid @ W2 + b2 (masked); prev[row]+=h*uw; g_st[row]=h (scatter)
// ---------------------------------------------------------------------------
template<int KDIM, int NDIM, int MODE>
__global__ __launch_bounds__(256, 2) void gemm_kernel(
    const float* __restrict__ Bw,
    const float* __restrict__ bias,
    const float* __restrict__ mask,
    float* __restrict__ out_prev,
    int t)
{
    const int nact = g_nact[t];
    const int bm = blockIdx.y * 128;
    if (bm >= nact) return;
    const int bn = blockIdx.x * 128;

    __shared__ float As[2][128][20];   // [m][k], padded row (conflict-free)
    __shared__ float Bs[2][16][128];   // [k][n]

    const float* __restrict__ Aptr = (MODE == 0) ? g_s : g_hmid;

    const int tid  = threadIdx.x;
    const int am_l = tid >> 1;            // 0..127
    const int ac   = (tid & 1) * 8;       // k chunk 0 or 8
    const int bk_l = tid >> 4;            // 0..15
    const int bn_l = (tid & 15) * 4;      // n chunk

    const float* a_base = Aptr + (size_t)(bm + am_l) * KDIM + ac;
    const float* b_base = Bw + (size_t)bk_l * NDIM + bn + bn_l;

    #define LOAD_TILES(buf, k0)                                          \
        do {                                                             \
            const float* ap_ = a_base + (k0);                            \
            cp_async16(&As[buf][am_l][ac],     ap_);                     \
            cp_async16(&As[buf][am_l][ac + 4], ap_ + 4);                 \
            const float* bp_ = b_base + (size_t)(k0) * NDIM;             \
            cp_async16(&Bs[buf][bk_l][bn_l],      bp_);                  \
            cp_async16(&Bs[buf][bk_l][bn_l + 64], bp_ + 64);             \
            asm volatile("cp.async.commit_group;\n" ::: "memory");       \
        } while (0)

    LOAD_TILES(0, 0);
    asm volatile("cp.async.wait_group 0;\n" ::: "memory");
    __syncthreads();

    const int tx = tid & 15;
    const int ty = tid >> 4;
    float acc[8][8] = {};
    constexpr int KT = KDIM / BK;

    #pragma unroll 1
    for (int kt = 0; kt < KT; ++kt) {
        const int cur = kt & 1;
        if (kt + 1 < KT) LOAD_TILES(cur ^ 1, (kt + 1) * BK);

        #pragma unroll
        for (int kq = 0; kq < 4; ++kq) {
            float a_reg[8][4];
            #pragma unroll
            for (int i = 0; i < 4; ++i) {
                float4 v0 = *(const float4*)&As[cur][ty * 4 + i][kq * 4];
                float4 v1 = *(const float4*)&As[cur][64 + ty * 4 + i][kq * 4];
                a_reg[i][0] = v0.x; a_reg[i][1] = v0.y;
                a_reg[i][2] = v0.z; a_reg[i][3] = v0.w;
                a_reg[4 + i][0] = v1.x; a_reg[4 + i][1] = v1.y;
                a_reg[4 + i][2] = v1.z; a_reg[4 + i][3] = v1.w;
            }
            #pragma unroll
            for (int kk = 0; kk < 4; ++kk) {
                float4 fb0 = *(const float4*)&Bs[cur][kq * 4 + kk][tx * 4];
                float4 fb1 = *(const float4*)&Bs[cur][kq * 4 + kk][64 + tx * 4];
                float b[8] = {fb0.x, fb0.y, fb0.z, fb0.w,
                              fb1.x, fb1.y, fb1.z, fb1.w};
                #pragma unroll
                for (int i = 0; i < 8; ++i)
                    #pragma unroll
                    for (int j = 0; j < 8; ++j)
                        acc[i][j] += a_reg[i][kk] * b[j];
            }
        }
        asm volatile("cp.async.wait_group 0;\n" ::: "memory");
        __syncthreads();
    }
    #undef LOAD_TILES

    #pragma unroll
    for (int i = 0; i < 8; ++i) {
        const int mloc = (i < 4) ? (ty * 4 + i) : (64 + ty * 4 + (i - 4));
        const int m = bm + mloc;
        if (m >= nact) continue;
        if (MODE == 0) {
            float* outp = g_hmid + (size_t)m * NDIM + bn;
            #pragma unroll
            for (int jj = 0; jj < 2; ++jj) {
                int cc = jj * 64 + tx * 4;
                float4 v;
                v.x = fmaxf(acc[i][jj * 4 + 0] + bias[bn + cc + 0], 0.0f);
                v.y = fmaxf(acc[i][jj * 4 + 1] + bias[bn + cc + 1], 0.0f);
                v.z = fmaxf(acc[i][jj * 4 + 2] + bias[bn + cc + 2], 0.0f);
                v.w = fmaxf(acc[i][jj * 4 + 3] + bias[bn + cc + 3], 0.0f);
                *(float4*)(outp + cc) = v;
            }
        } else {
            const int row = g_idx[m];
            const float mk  = mask[row];
            const float uwv = g_uw[row];
            float* pp = out_prev + (size_t)row * NDIM + bn;
            float* sp = g_st     + (size_t)row * NDIM + bn;
            #pragma unroll
            for (int jj = 0; jj < 2; ++jj) {
                int cc = jj * 64 + tx * 4;
                float4 h;
                h.x = (acc[i][jj * 4 + 0] + bias[bn + cc + 0]) * mk;
                h.y = (acc[i][jj * 4 + 1] + bias[bn + cc + 1]) * mk;
                h.z = (acc[i][jj * 4 + 2] + bias[bn + cc + 2]) * mk;
                h.w = (acc[i][jj * 4 + 3] + bias[bn + cc + 3]) * mk;
                float4 pv = *(const float4*)(pp + cc);
                pv.x += h.x * uwv; pv.y += h.y * uwv;
                pv.z += h.z * uwv; pv.w += h.w * uwv;
                *(float4*)(pp + cc) = pv;
                *(float4*)(sp + cc) = h;
            }
        }
    }
}

// ---------------------------------------------------------------------------
extern "C" void kernel_launch(void* const* d_in, const int* in_sizes, int n_in,
                              void* d_out, int out_size)
{
    const float* state    = (const float*)d_in[0];
    const float* mask     = (const float*)d_in[1];
    const float* step_emb = (const float*)d_in[2];
    const float* Wp       = (const float*)d_in[3];
    const float* bp       = (const float*)d_in[4];
    const float* W1       = (const float*)d_in[5];
    const float* b1       = (const float*)d_in[6];
    const float* W2       = (const float*)d_in[7];
    const float* b2       = (const float*)d_in[8];

    float* out     = (float*)d_out;
    float* out_nup = out + (size_t)MM * DD;
    float* out_rem = out_nup + MM;

    init_kernel<<<(MM * DD + 255) / 256, 256>>>(state, out);

    dim3 g1(FF / 128, MM / 128);   // (16, 128)
    dim3 g2(DD / 128, MM / 128);   // (4, 128)
    const int prep_blocks = (MM * (DD / 4) + 255) / 256;   // 8192

    for (int t = 0; t < NITER; ++t) {
        ponder_kernel<<<MM / 8, 256>>>(step_emb, Wp, bp, out_nup, out_rem, t);
        prep_kernel<<<prep_blocks, 256>>>(step_emb, t);
        gemm_kernel<DD, FF, 0><<<g1, 256>>>(W1, b1, nullptr, nullptr, t);
        gemm_kernel<FF, DD, 1><<<g2, 256>>>(W2, b2, mask, out, t);
    }
}

// round 3
// speedup vs baseline: 1.5683x; 1.1367x over previous
#include <cuda_runtime.h>
#include <math.h>
#include <stdint.h>

#define MM   16384
#define DD   512
#define FF   2048
#define NITER 11
#define THRESH (1.0f - 0.01f)
#define PITCH 20      // smem row pitch in floats (conflict-free for frag LDS)

// Device scratch (no allocation allowed)
__device__ float g_st[(size_t)MM * DD];        // carried state, original order
__device__ float g_s_hi[(size_t)MM * DD];      // compact split s
__device__ float g_s_lo[(size_t)MM * DD];
__device__ float g_h_hi[(size_t)MM * FF];      // compact split hidden
__device__ float g_h_lo[(size_t)MM * FF];
__device__ float g_w1_hi[(size_t)FF * DD];     // W1^T split: [F][D]
__device__ float g_w1_lo[(size_t)FF * DD];
__device__ float g_w2_hi[(size_t)DD * FF];     // W2^T split: [D][F]
__device__ float g_w2_lo[(size_t)DD * FF];
__device__ float g_hp[MM];
__device__ float g_uw[MM];
__device__ int   g_idx[MM];
__device__ int   g_nact[NITER + 1];
__device__ int   g_flag[NITER + 1];

// ---------------------------------------------------------------------------
__device__ __forceinline__ void cp_async16(void* smem, const void* gmem)
{
    unsigned s = (unsigned)__cvta_generic_to_shared(smem);
    asm volatile("cp.async.cg.shared.global [%0], [%1], 16;\n" :: "r"(s), "l"(gmem));
}

__device__ __forceinline__ float2 tf32_split(float v)
{
    unsigned h;
    asm("cvt.rna.tf32.f32 %0, %1;" : "=r"(h) : "f"(v));
    float hf = __uint_as_float(h);
    float r = v - hf;
    unsigned l;
    asm("cvt.rna.tf32.f32 %0, %1;" : "=r"(l) : "f"(r));
    return make_float2(hf, __uint_as_float(l));
}

__device__ __forceinline__ void mma_tf32(float4& d,
    unsigned a0, unsigned a1, unsigned a2, unsigned a3,
    unsigned b0, unsigned b1)
{
    asm volatile(
        "mma.sync.aligned.m16n8k8.row.col.f32.tf32.tf32.f32 "
        "{%0,%1,%2,%3}, {%4,%5,%6,%7}, {%8,%9}, {%0,%1,%2,%3};"
        : "+f"(d.x), "+f"(d.y), "+f"(d.z), "+f"(d.w)
        : "r"(a0), "r"(a1), "r"(a2), "r"(a3), "r"(b0), "r"(b1));
}

// ---------------------------------------------------------------------------
__global__ void init_kernel(const float* __restrict__ state, float* __restrict__ out)
{
    size_t i = (size_t)blockIdx.x * blockDim.x + threadIdx.x;
    if (i < (size_t)MM * DD) {
        g_st[i] = state[i];
        out[i]  = 0.0f;
    }
    if (i < MM) {
        g_hp[i] = 0.0f;
        out[(size_t)MM * DD + i] = 0.0f;
        out[(size_t)MM * DD + MM + i] = 0.0f;
    }
    if (i <= NITER) { g_flag[i] = (i == 0) ? 1 : 0; g_nact[i] = 0; }
}

// Transpose + split weights: W[K][N] -> Th/Tl [N][K]
__global__ void wsplit_kernel(const float* __restrict__ W,
                              float* __restrict__ Th, float* __restrict__ Tl,
                              int K, int N)
{
    int i = blockIdx.x * blockDim.x + threadIdx.x;
    if (i >= K * N) return;
    int n = i / K, k = i - n * K;
    float2 s = tf32_split(W[(size_t)k * N + n]);
    Th[i] = s.x; Tl[i] = s.y;
}

// ---------------------------------------------------------------------------
__global__ void ponder_kernel(const float* __restrict__ step_emb,
                              const float* __restrict__ Wp,
                              const float* __restrict__ bp,
                              float* __restrict__ out_nup,
                              float* __restrict__ out_rem,
                              int t)
{
    if (!g_flag[t]) return;
    int row  = blockIdx.x * 8 + (threadIdx.x >> 5);
    int lane = threadIdx.x & 31;

    __shared__ int s_active;
    if (threadIdx.x == 0) s_active = 0;
    __syncthreads();

    float hp = g_hp[row];
    if (hp < 1.0f) {
        const float4* st4 = (const float4*)(g_st + (size_t)row * DD);
        const float4* e4  = (const float4*)(step_emb + (size_t)t * DD);
        const float4* w4  = (const float4*)Wp;

        float dot = 0.0f;
        #pragma unroll
        for (int i = lane; i < DD / 4; i += 32) {
            float4 s = st4[i], e = e4[i], w = w4[i];
            dot += (s.x + e.x) * w.x + (s.y + e.y) * w.y
                 + (s.z + e.z) * w.z + (s.w + e.w) * w.w;
        }
        #pragma unroll
        for (int o = 16; o; o >>= 1) dot += __shfl_xor_sync(0xffffffffu, dot, o);

        if (lane == 0) {
            float p = 1.0f / (1.0f + expf(-(dot + bp[0])));
            float q  = hp + p;
            float nh = (q >  THRESH) ? 1.0f : 0.0f;
            float st = (q <= THRESH) ? 1.0f : 0.0f;
            hp = hp + p * st;
            float rem = out_rem[row] + nh * (1.0f - hp);
            hp = hp + nh * rem;
            out_nup[row] += 1.0f;
            g_hp[row]    = hp;
            out_rem[row] = rem;
            g_uw[row]    = p * st + nh * rem;
            int pos = atomicAdd(&g_nact[t], 1);
            g_idx[pos] = row;
            if (hp < 1.0f) atomicOr(&s_active, 1);
        }
    }
    __syncthreads();
    if (threadIdx.x == 0 && s_active) atomicOr(&g_flag[t + 1], 1);
}

// ---------------------------------------------------------------------------
// Prep: gather active rows, s = st+emb, write tf32 split
// ---------------------------------------------------------------------------
__global__ void prep_kernel(const float* __restrict__ step_emb, int t)
{
    int nact = g_nact[t];
    int gid = blockIdx.x * blockDim.x + threadIdx.x;
    int r = gid >> 7;
    if (r >= nact) return;
    int c = (gid & 127) << 2;
    int row = g_idx[r];
    float4 s = *(const float4*)(g_st + (size_t)row * DD + c);
    float4 e = *(const float4*)(step_emb + (size_t)t * DD + c);
    float2 p0 = tf32_split(s.x + e.x);
    float2 p1 = tf32_split(s.y + e.y);
    float2 p2 = tf32_split(s.z + e.z);
    float2 p3 = tf32_split(s.w + e.w);
    *(float4*)(g_s_hi + (size_t)r * DD + c) = make_float4(p0.x, p1.x, p2.x, p3.x);
    *(float4*)(g_s_lo + (size_t)r * DD + c) = make_float4(p0.y, p1.y, p2.y, p3.y);
}

// ---------------------------------------------------------------------------
// Tensor-core GEMM: 128x128 CTA tile, BK=16, tf32 3-term split.
// MODE 0: hmid = relu(s @ W1 + b1), epilogue writes tf32-split hi/lo
// MODE 1: h = hmid @ W2 + b2 (masked); prev[row]+=h*uw; g_st[row]=h
// ---------------------------------------------------------------------------
#define STILE (128 * PITCH)          // floats per smem matrix
#define SSTAGE (4 * STILE)           // Ah, Al, Bh, Bl
#define SMEM_BYTES (2 * SSTAGE * 4)  // double buffered = 81920 B

template<int KDIM, int NDIM, int MODE>
__global__ __launch_bounds__(256, 2) void gemm_tc(
    const float* __restrict__ bias,
    const float* __restrict__ mask,
    float* __restrict__ out_prev,
    int t)
{
    const int nact = g_nact[t];
    const int bm = blockIdx.y * 128;
    if (bm >= nact) return;
    const int bn = blockIdx.x * 128;

    extern __shared__ float smem[];

    const float* __restrict__ Ahg = (MODE == 0) ? g_s_hi : g_h_hi;
    const float* __restrict__ Alg = (MODE == 0) ? g_s_lo : g_h_lo;
    const float* __restrict__ Bhg = (MODE == 0) ? g_w1_hi : g_w2_hi;
    const float* __restrict__ Blg = (MODE == 0) ? g_w1_lo : g_w2_lo;

    const int tid  = threadIdx.x;
    const int lrow = tid >> 1;            // 0..127
    const int lco  = (tid & 1) * 8;       // 0 or 8

    const float* a_hi = Ahg + (size_t)(bm + lrow) * KDIM + lco;
    const float* a_lo = Alg + (size_t)(bm + lrow) * KDIM + lco;
    const float* b_hi = Bhg + (size_t)(bn + lrow) * KDIM + lco;
    const float* b_lo = Blg + (size_t)(bn + lrow) * KDIM + lco;
    const unsigned sdst = lrow * PITCH + lco;

    #define LOAD_STAGE(buf, k0)                                              \
        do {                                                                 \
            float* base_ = smem + (buf) * SSTAGE;                            \
            cp_async16(base_ + sdst,               a_hi + (k0));             \
            cp_async16(base_ + sdst + 4,           a_hi + (k0) + 4);         \
            cp_async16(base_ + STILE + sdst,       a_lo + (k0));             \
            cp_async16(base_ + STILE + sdst + 4,   a_lo + (k0) + 4);         \
            cp_async16(base_ + 2*STILE + sdst,     b_hi + (k0));             \
            cp_async16(base_ + 2*STILE + sdst + 4, b_hi + (k0) + 4);         \
            cp_async16(base_ + 3*STILE + sdst,     b_lo + (k0));             \
            cp_async16(base_ + 3*STILE + sdst + 4, b_lo + (k0) + 4);         \
            asm volatile("cp.async.commit_group;\n" ::: "memory");           \
        } while (0)

    LOAD_STAGE(0, 0);

    const int lane = tid & 31;
    const int w    = tid >> 5;
    const int wm   = (w >> 2) * 64;    // warp m offset (0 or 64)
    const int wn   = (w & 3) * 32;     // warp n offset
    const int g    = lane >> 2;
    const int tq   = lane & 3;

    float4 acc[4][4];
    #pragma unroll
    for (int i = 0; i < 4; ++i)
        #pragma unroll
        for (int j = 0; j < 4; ++j)
            acc[i][j] = make_float4(0.f, 0.f, 0.f, 0.f);

    asm volatile("cp.async.wait_group 0;\n" ::: "memory");
    __syncthreads();

    constexpr int KT = KDIM / 16;
    #pragma unroll 1
    for (int kt = 0; kt < KT; ++kt) {
        const int cur = kt & 1;
        if (kt + 1 < KT) LOAD_STAGE(cur ^ 1, (kt + 1) * 16);

        const float* Ah = smem + cur * SSTAGE;
        const float* Al = Ah + STILE;
        const float* Bh = Al + STILE;
        const float* Bl = Bh + STILE;

        #pragma unroll
        for (int sub = 0; sub < 2; ++sub) {
            const int kb = sub * 8;
            unsigned bh[4][2], bl[4][2];
            #pragma unroll
            for (int nj = 0; nj < 4; ++nj) {
                int n0 = (wn + nj * 8 + g) * PITCH + kb + tq;
                bh[nj][0] = __float_as_uint(Bh[n0]);
                bh[nj][1] = __float_as_uint(Bh[n0 + 4]);
                bl[nj][0] = __float_as_uint(Bl[n0]);
                bl[nj][1] = __float_as_uint(Bl[n0 + 4]);
            }
            #pragma unroll
            for (int mi = 0; mi < 4; ++mi) {
                int r0 = (wm + mi * 16 + g) * PITCH + kb + tq;
                int r1 = r0 + 8 * PITCH;
                unsigned ah0 = __float_as_uint(Ah[r0]);
                unsigned ah1 = __float_as_uint(Ah[r1]);
                unsigned ah2 = __float_as_uint(Ah[r0 + 4]);
                unsigned ah3 = __float_as_uint(Ah[r1 + 4]);
                unsigned al0 = __float_as_uint(Al[r0]);
                unsigned al1 = __float_as_uint(Al[r1]);
                unsigned al2 = __float_as_uint(Al[r0 + 4]);
                unsigned al3 = __float_as_uint(Al[r1 + 4]);
                #pragma unroll
                for (int nj = 0; nj < 4; ++nj) {
                    mma_tf32(acc[mi][nj], ah0, ah1, ah2, ah3, bh[nj][0], bh[nj][1]);
                    mma_tf32(acc[mi][nj], ah0, ah1, ah2, ah3, bl[nj][0], bl[nj][1]);
                    mma_tf32(acc[mi][nj], al0, al1, al2, al3, bh[nj][0], bh[nj][1]);
                }
            }
        }
        asm volatile("cp.async.wait_group 0;\n" ::: "memory");
        __syncthreads();
    }
    #undef LOAD_STAGE

    // Epilogue: acc[mi][nj] = D rows {g, g+8}, cols {2t, 2t+1} of tile (mi,nj)
    #pragma unroll
    for (int mi = 0; mi < 4; ++mi) {
        const int m0 = bm + wm + mi * 16 + g;
        const int m1 = m0 + 8;
        #pragma unroll
        for (int half = 0; half < 2; ++half) {
            const int m = half ? m1 : m0;
            if (m >= nact) continue;
            if (MODE == 0) {
                #pragma unroll
                for (int nj = 0; nj < 4; ++nj) {
                    const int col = bn + wn + nj * 8 + 2 * tq;
                    float v0 = half ? acc[mi][nj].z : acc[mi][nj].x;
                    float v1 = half ? acc[mi][nj].w : acc[mi][nj].y;
                    v0 = fmaxf(v0 + bias[col], 0.0f);
                    v1 = fmaxf(v1 + bias[col + 1], 0.0f);
                    float2 s0 = tf32_split(v0);
                    float2 s1 = tf32_split(v1);
                    *(float2*)(g_h_hi + (size_t)m * NDIM + col) = make_float2(s0.x, s1.x);
                    *(float2*)(g_h_lo + (size_t)m * NDIM + col) = make_float2(s0.y, s1.y);
                }
            } else {
                const int row = g_idx[m];
                const float mk  = mask[row];
                const float uwv = g_uw[row];
                #pragma unroll
                for (int nj = 0; nj < 4; ++nj) {
                    const int col = bn + wn + nj * 8 + 2 * tq;
                    float v0 = half ? acc[mi][nj].z : acc[mi][nj].x;
                    float v1 = half ? acc[mi][nj].w : acc[mi][nj].y;
                    float h0 = (v0 + bias[col])     * mk;
                    float h1 = (v1 + bias[col + 1]) * mk;
                    float* pp = out_prev + (size_t)row * NDIM + col;
                    float* sp = g_st     + (size_t)row * NDIM + col;
                    float2 pv = *(const float2*)pp;
                    pv.x += h0 * uwv;
                    pv.y += h1 * uwv;
                    *(float2*)pp = pv;
                    *(float2*)sp = make_float2(h0, h1);
                }
            }
        }
    }
}

// ---------------------------------------------------------------------------
extern "C" void kernel_launch(void* const* d_in, const int* in_sizes, int n_in,
                              void* d_out, int out_size)
{
    const float* state    = (const float*)d_in[0];
    const float* mask     = (const float*)d_in[1];
    const float* step_emb = (const float*)d_in[2];
    const float* Wp       = (const float*)d_in[3];
    const float* bp       = (const float*)d_in[4];
    const float* W1       = (const float*)d_in[5];
    const float* b1       = (const float*)d_in[6];
    const float* W2       = (const float*)d_in[7];
    const float* b2       = (const float*)d_in[8];

    float* out     = (float*)d_out;
    float* out_nup = out + (size_t)MM * DD;
    float* out_rem = out_nup + MM;

    cudaFuncSetAttribute(gemm_tc<DD, FF, 0>,
        cudaFuncAttributeMaxDynamicSharedMemorySize, SMEM_BYTES);
    cudaFuncSetAttribute(gemm_tc<FF, DD, 1>,
        cudaFuncAttributeMaxDynamicSharedMemorySize, SMEM_BYTES);

    init_kernel<<<(MM * DD + 255) / 256, 256>>>(state, out);

    // One-time weight transpose+split (per launch; deterministic)
    {
        float *w1h, *w1l, *w2h, *w2l;
        cudaGetSymbolAddress((void**)&w1h, g_w1_hi);
        cudaGetSymbolAddress((void**)&w1l, g_w1_lo);
        cudaGetSymbolAddress((void**)&w2h, g_w2_hi);
        cudaGetSymbolAddress((void**)&w2l, g_w2_lo);
        wsplit_kernel<<<(DD * FF + 255) / 256, 256>>>(W1, w1h, w1l, DD, FF);
        wsplit_kernel<<<(FF * DD + 255) / 256, 256>>>(W2, w2h, w2l, FF, DD);
    }

    dim3 g1(FF / 128, MM / 128);   // (16, 128)
    dim3 g2(DD / 128, MM / 128);   // (4, 128)
    const int prep_blocks = (MM * (DD / 4) + 255) / 256;

    for (int t = 0; t < NITER; ++t) {
        ponder_kernel<<<MM / 8, 256>>>(step_emb, Wp, bp, out_nup, out_rem, t);
        prep_kernel<<<prep_blocks, 256>>>(step_emb, t);
        gemm_tc<DD, FF, 0><<<g1, 256, SMEM_BYTES>>>(b1, nullptr, nullptr, t);
        gemm_tc<FF, DD, 1><<<g2, 256, SMEM_BYTES>>>(b2, mask, out, t);
    }
}

// round 5
// speedup vs baseline: 2.1877x; 1.3950x over previous
#include <cuda_runtime.h>
#include <cuda_fp16.h>
#include <math.h>
#include <stdint.h>

#define MM   16384
#define DD   512
#define FF   2048
#define NITER 11
#define THRESH (1.0f - 0.01f)

// SMEM tile geometry (fp16): 128 rows x (32 data + 8 pad) halves = 80B pitch
#define AP       40                      // halves per row
#define TILE_HB  (128 * AP * 2)          // 10240 B per matrix
#define STAGE_B  (4 * TILE_HB)           // Ah, Al, Bh, Bl = 40960 B
#define NSTAGE   3
#define DYN_SMEM (NSTAGE * STAGE_B)      // 122880 B

// Device scratch
__device__ float  g_st[(size_t)MM * DD];       // fp32 carried state
__device__ __half g_s_hi[(size_t)MM * DD];     // compact split s
__device__ __half g_s_lo[(size_t)MM * DD];
__device__ __half g_h_hi[(size_t)MM * FF];     // compact split hidden
__device__ __half g_h_lo[(size_t)MM * FF];
__device__ __half g_w1_hi[(size_t)FF * DD];    // W1^T [F][D]
__device__ __half g_w1_lo[(size_t)FF * DD];
__device__ __half g_w2_hi[(size_t)DD * FF];    // W2^T [D][F]
__device__ __half g_w2_lo[(size_t)DD * FF];
__device__ float  g_hp[MM];
__device__ float  g_uw[MM];
__device__ int    g_idx[MM];
__device__ int    g_nact[NITER + 1];
__device__ int    g_flag[NITER + 1];

// ---------------------------------------------------------------------------
__device__ __forceinline__ void cp_async16_s(uint32_t dst, const void* src) {
    asm volatile("cp.async.cg.shared.global [%0], [%1], 16;\n" :: "r"(dst), "l"(src));
}
template<int N> __device__ __forceinline__ void cp_wait() {
    asm volatile("cp.async.wait_group %0;\n" :: "n"(N) : "memory");
}

__device__ __forceinline__ void f16_split(float v, __half& hi, __half& lo) {
    hi = __float2half_rn(v);
    lo = __float2half_rn(v - __half2float(hi));
}

__device__ __forceinline__ void ldsm_x4(uint32_t& r0, uint32_t& r1,
                                        uint32_t& r2, uint32_t& r3, uint32_t a) {
    asm volatile("ldmatrix.sync.aligned.m8n8.x4.shared.b16 {%0,%1,%2,%3}, [%4];"
                 : "=r"(r0), "=r"(r1), "=r"(r2), "=r"(r3) : "r"(a));
}

__device__ __forceinline__ void mma_f16(float4& d,
    uint32_t a0, uint32_t a1, uint32_t a2, uint32_t a3,
    uint32_t b0, uint32_t b1) {
    asm volatile(
        "mma.sync.aligned.m16n8k16.row.col.f32.f16.f16.f32 "
        "{%0,%1,%2,%3}, {%4,%5,%6,%7}, {%8,%9}, {%0,%1,%2,%3};"
        : "+f"(d.x), "+f"(d.y), "+f"(d.z), "+f"(d.w)
        : "r"(a0), "r"(a1), "r"(a2), "r"(a3), "r"(b0), "r"(b1));
}

// ---------------------------------------------------------------------------
__global__ void init_kernel(const float* __restrict__ state, float* __restrict__ out)
{
    size_t i = (size_t)blockIdx.x * blockDim.x + threadIdx.x;
    if (i < (size_t)MM * DD) {
        g_st[i] = state[i];
        out[i]  = 0.0f;
    }
    if (i < MM) {
        g_hp[i] = 0.0f;
        out[(size_t)MM * DD + i] = 0.0f;
        out[(size_t)MM * DD + MM + i] = 0.0f;
    }
    if (i <= NITER) { g_flag[i] = (i == 0) ? 1 : 0; g_nact[i] = 0; }
}

// Transpose + split weights: W[K][N] -> Th/Tl [N][K] fp16
__global__ void wsplit_kernel(const float* __restrict__ W,
                              __half* __restrict__ Th, __half* __restrict__ Tl,
                              int K, int N)
{
    int i = blockIdx.x * blockDim.x + threadIdx.x;
    if (i >= K * N) return;
    int n = i / K, k = i - n * K;
    __half hi, lo;
    f16_split(W[(size_t)k * N + n], hi, lo);
    Th[i] = hi; Tl[i] = lo;
}

// ---------------------------------------------------------------------------
__global__ void ponder_kernel(const float* __restrict__ step_emb,
                              const float* __restrict__ Wp,
                              const float* __restrict__ bp,
                              float* __restrict__ out_nup,
                              float* __restrict__ out_rem,
                              int t)
{
    if (!g_flag[t]) return;
    int row  = blockIdx.x * 8 + (threadIdx.x >> 5);
    int lane = threadIdx.x & 31;

    __shared__ int s_active;
    if (threadIdx.x == 0) s_active = 0;
    __syncthreads();

    float hp = g_hp[row];
    if (hp < 1.0f) {
        const float4* st4 = (const float4*)(g_st + (size_t)row * DD);
        const float4* e4  = (const float4*)(step_emb + (size_t)t * DD);
        const float4* w4  = (const float4*)Wp;

        float dot = 0.0f;
        #pragma unroll
        for (int i = lane; i < DD / 4; i += 32) {
            float4 s = st4[i], e = e4[i], w = w4[i];
            dot += (s.x + e.x) * w.x + (s.y + e.y) * w.y
                 + (s.z + e.z) * w.z + (s.w + e.w) * w.w;
        }
        #pragma unroll
        for (int o = 16; o; o >>= 1) dot += __shfl_xor_sync(0xffffffffu, dot, o);

        if (lane == 0) {
            float p = 1.0f / (1.0f + expf(-(dot + bp[0])));
            float q  = hp + p;
            float nh = (q >  THRESH) ? 1.0f : 0.0f;
            float st = (q <= THRESH) ? 1.0f : 0.0f;
            hp = hp + p * st;
            float rem = out_rem[row] + nh * (1.0f - hp);
            hp = hp + nh * rem;
            out_nup[row] += 1.0f;
            g_hp[row]    = hp;
            out_rem[row] = rem;
            g_uw[row]    = p * st + nh * rem;
            int pos = atomicAdd(&g_nact[t], 1);
            g_idx[pos] = row;
            if (hp < 1.0f) atomicOr(&s_active, 1);
        }
    }
    __syncthreads();
    if (threadIdx.x == 0 && s_active) atomicOr(&g_flag[t + 1], 1);
}

// ---------------------------------------------------------------------------
// Prep: gather active rows, s = st+emb, write fp16 split
// ---------------------------------------------------------------------------
__global__ void prep_kernel(const float* __restrict__ step_emb, int t)
{
    int nact = g_nact[t];
    int gid = blockIdx.x * blockDim.x + threadIdx.x;
    int r = gid >> 7;
    if (r >= nact) return;
    int c = (gid & 127) << 2;
    int row = g_idx[r];
    float4 s = *(const float4*)(g_st + (size_t)row * DD + c);
    float4 e = *(const float4*)(step_emb + (size_t)t * DD + c);
    __half h0, l0, h1, l1, h2, l2, h3, l3;
    f16_split(s.x + e.x, h0, l0);
    f16_split(s.y + e.y, h1, l1);
    f16_split(s.z + e.z, h2, l2);
    f16_split(s.w + e.w, h3, l3);
    __half2* ph = (__half2*)(g_s_hi + (size_t)r * DD + c);
    __half2* pl = (__half2*)(g_s_lo + (size_t)r * DD + c);
    ph[0] = __halves2half2(h0, h1); ph[1] = __halves2half2(h2, h3);
    pl[0] = __halves2half2(l0, l1); pl[1] = __halves2half2(l2, l3);
}

// ---------------------------------------------------------------------------
// HMMA fp16-split GEMM: 128x128 CTA, BK=32, 3-stage cp.async, ldmatrix frags.
// MODE 0: g_h = relu(g_s @ W1' + b1)  (fp16-split output)
// MODE 1: h = g_h @ W2' + b2 (masked); out_prev[row]+=h*uw; g_st[row]=h
// ---------------------------------------------------------------------------
template<int KDIM, int NDIM, int MODE>
__global__ __launch_bounds__(256) void gemm_hmma(
    const float* __restrict__ bias,
    const float* __restrict__ mask,
    float* __restrict__ out_prev, int t)
{
    const int nact = g_nact[t];
    const int bm = blockIdx.y * 128;
    if (bm >= nact) return;
    const int bn = blockIdx.x * 128;

    extern __shared__ unsigned char smem_raw[];
    uint32_t sb;
    asm("{ .reg .u64 tt; cvta.to.shared.u64 tt, %1; cvt.u32.u64 %0, tt; }"
        : "=r"(sb) : "l"(smem_raw));

    const int tid = threadIdx.x;

    // ---- global source pointers per loader tile (Ah, Al, Bh, Bl) ----
    const __half* Ahg = ((MODE == 0) ? g_s_hi : g_h_hi) + (size_t)bm * KDIM;
    const __half* Alg = ((MODE == 0) ? g_s_lo : g_h_lo) + (size_t)bm * KDIM;
    const __half* Bhg = ((MODE == 0) ? g_w1_hi : g_w2_hi) + (size_t)bn * KDIM;
    const __half* Blg = ((MODE == 0) ? g_w1_lo : g_w2_lo) + (size_t)bn * KDIM;
    const int tl = tid >> 6;
    const __half* tp = (tl == 0) ? Ahg : (tl == 1) ? Alg : (tl == 2) ? Bhg : Blg;
    const int u = tid & 63;
    const uint32_t tile_off = (uint32_t)tl * TILE_HB;

    // 512 16B-chunks per matrix; this thread's 8 chunks
    #define LOAD_STAGE(slot, k0)                                               \
        do {                                                                   \
            uint32_t dst_ = sb + (uint32_t)(slot) * STAGE_B + tile_off;        \
            _Pragma("unroll")                                                  \
            for (int j_ = 0; j_ < 8; ++j_) {                                   \
                int ch_ = u + j_ * 64;                                         \
                int row_ = ch_ >> 2, c_ = ch_ & 3;                             \
                cp_async16_s(dst_ + (uint32_t)(row_ * (AP * 2) + c_ * 16),     \
                             tp + (size_t)row_ * KDIM + (k0) + c_ * 8);        \
            }                                                                  \
            asm volatile("cp.async.commit_group;" ::: "memory");               \
        } while (0)

    constexpr int KT = KDIM / 32;
    LOAD_STAGE(0, 0);
    LOAD_STAGE(1, 32);
    cp_wait<1>();
    __syncthreads();

    // ---- warp tiling: 8 warps, 64x32 each ----
    const int lane = tid & 31;
    const int w    = tid >> 5;
    const int wm   = (w >> 2) * 64;
    const int wn   = (w & 3) * 32;
    const int lr   = lane & 15;           // ldmatrix row within 16
    const int lc   = (lane >> 4) * 8;     // ldmatrix k-offset (0/8)

    float4 acc[4][4];
    #pragma unroll
    for (int i = 0; i < 4; ++i)
        #pragma unroll
        for (int j = 0; j < 4; ++j)
            acc[i][j] = make_float4(0.f, 0.f, 0.f, 0.f);

    #pragma unroll 1
    for (int kt = 0; kt < KT; ++kt) {
        const uint32_t stg = sb + (uint32_t)(kt % NSTAGE) * STAGE_B;
        const bool have_next_load = (kt + 2 <= KT - 1);
        if (have_next_load) LOAD_STAGE((kt + 2) % NSTAGE, (kt + 2) * 32);

        #pragma unroll
        for (int sub = 0; sub < 2; ++sub) {
            const int k0 = sub * 16;
            // B fragments: hi & lo, 4 nj tiles via 2 ldmatrix.x4 each
            uint32_t bh[4][2], bl[4][2];
            #pragma unroll
            for (int njp = 0; njp < 2; ++njp) {
                uint32_t addr = stg + 2 * TILE_HB
                    + (uint32_t)(((wn + njp * 16 + lr) * AP + k0 + lc) * 2);
                uint32_t r0, r1, r2, r3;
                ldsm_x4(r0, r1, r2, r3, addr);
                bh[njp * 2][0] = r0; bh[njp * 2][1] = r2;
                bh[njp * 2 + 1][0] = r1; bh[njp * 2 + 1][1] = r3;
                addr += TILE_HB;
                ldsm_x4(r0, r1, r2, r3, addr);
                bl[njp * 2][0] = r0; bl[njp * 2][1] = r2;
                bl[njp * 2 + 1][0] = r1; bl[njp * 2 + 1][1] = r3;
            }
            #pragma unroll
            for (int mi = 0; mi < 4; ++mi) {
                uint32_t addr = stg
                    + (uint32_t)(((wm + mi * 16 + lr) * AP + k0 + lc) * 2);
                uint32_t ah0, ah1, ah2, ah3, al0, al1, al2, al3;
                ldsm_x4(ah0, ah1, ah2, ah3, addr);
                ldsm_x4(al0, al1, al2, al3, addr + TILE_HB);
                #pragma unroll
                for (int nj = 0; nj < 4; ++nj) {
                    mma_f16(acc[mi][nj], ah0, ah1, ah2, ah3, bh[nj][0], bh[nj][1]);
                    mma_f16(acc[mi][nj], ah0, ah1, ah2, ah3, bl[nj][0], bl[nj][1]);
                    mma_f16(acc[mi][nj], al0, al1, al2, al3, bh[nj][0], bh[nj][1]);
                }
            }
        }

        if (kt + 1 <= KT - 1) {
            if (have_next_load) cp_wait<1>(); else cp_wait<0>();
            __syncthreads();
        }
    }
    #undef LOAD_STAGE

    // ---- epilogue: acc[mi][nj] -> rows {g,g+8}, cols {2q,2q+1} ----
    const int g = lane >> 2;
    const int q = lane & 3;
    #pragma unroll
    for (int mi = 0; mi < 4; ++mi) {
        #pragma unroll
        for (int half = 0; half < 2; ++half) {
            const int m = bm + wm + mi * 16 + g + half * 8;
            if (m >= nact) continue;
            if (MODE == 0) {
                #pragma unroll
                for (int nj = 0; nj < 4; ++nj) {
                    const int col = bn + wn + nj * 8 + 2 * q;
                    float v0 = half ? acc[mi][nj].z : acc[mi][nj].x;
                    float v1 = half ? acc[mi][nj].w : acc[mi][nj].y;
                    v0 = fmaxf(v0 + bias[col], 0.0f);
                    v1 = fmaxf(v1 + bias[col + 1], 0.0f);
                    __half h0, l0, h1, l1;
                    f16_split(v0, h0, l0);
                    f16_split(v1, h1, l1);
                    *(__half2*)(g_h_hi + (size_t)m * NDIM + col) = __halves2half2(h0, h1);
                    *(__half2*)(g_h_lo + (size_t)m * NDIM + col) = __halves2half2(l0, l1);
                }
            } else {
                const int row = g_idx[m];
                const float mk  = mask[row];
                const float uwv = g_uw[row];
                #pragma unroll
                for (int nj = 0; nj < 4; ++nj) {
                    const int col = bn + wn + nj * 8 + 2 * q;
                    float v0 = half ? acc[mi][nj].z : acc[mi][nj].x;
                    float v1 = half ? acc[mi][nj].w : acc[mi][nj].y;
                    float h0 = (v0 + bias[col])     * mk;
                    float h1 = (v1 + bias[col + 1]) * mk;
                    float* pp = out_prev + (size_t)row * NDIM + col;
                    float* sp = g_st     + (size_t)row * NDIM + col;
                    float2 pv = *(const float2*)pp;
                    pv.x += h0 * uwv;
                    pv.y += h1 * uwv;
                    *(float2*)pp = pv;
                    *(float2*)sp = make_float2(h0, h1);
                }
            }
        }
    }
}

// ---------------------------------------------------------------------------
extern "C" void kernel_launch(void* const* d_in, const int* in_sizes, int n_in,
                              void* d_out, int out_size)
{
    const float* state    = (const float*)d_in[0];
    const float* mask     = (const float*)d_in[1];
    const float* step_emb = (const float*)d_in[2];
    const float* Wp       = (const float*)d_in[3];
    const float* bp       = (const float*)d_in[4];
    const float* W1       = (const float*)d_in[5];
    const float* b1       = (const float*)d_in[6];
    const float* W2       = (const float*)d_in[7];
    const float* b2       = (const float*)d_in[8];

    float* out     = (float*)d_out;
    float* out_nup = out + (size_t)MM * DD;
    float* out_rem = out_nup + MM;

    cudaFuncSetAttribute(gemm_hmma<DD, FF, 0>,
        cudaFuncAttributeMaxDynamicSharedMemorySize, DYN_SMEM);
    cudaFuncSetAttribute(gemm_hmma<FF, DD, 1>,
        cudaFuncAttributeMaxDynamicSharedMemorySize, DYN_SMEM);

    init_kernel<<<(MM * DD + 255) / 256, 256>>>(state, out);

    {
        __half *w1h, *w1l, *w2h, *w2l;
        cudaGetSymbolAddress((void**)&w1h, g_w1_hi);
        cudaGetSymbolAddress((void**)&w1l, g_w1_lo);
        cudaGetSymbolAddress((void**)&w2h, g_w2_hi);
        cudaGetSymbolAddress((void**)&w2l, g_w2_lo);
        wsplit_kernel<<<(DD * FF + 255) / 256, 256>>>(W1, w1h, w1l, DD, FF);
        wsplit_kernel<<<(FF * DD + 255) / 256, 256>>>(W2, w2h, w2l, FF, DD);
    }

    dim3 g1(FF / 128, MM / 128);   // (16, 128)
    dim3 g2(DD / 128, MM / 128);   // (4, 128)
    const int prep_blocks = (MM * (DD / 4) + 255) / 256;

    for (int t = 0; t < NITER; ++t) {
        ponder_kernel<<<MM / 8, 256>>>(step_emb, Wp, bp, out_nup, out_rem, t);
        prep_kernel<<<prep_blocks, 256>>>(step_emb, t);
        gemm_hmma<DD, FF, 0><<<g1, 256, DYN_SMEM>>>(b1, nullptr, nullptr, t);
        gemm_hmma<FF, DD, 1><<<g2, 256, DYN_SMEM>>>(b2, mask, out, t);
    }
}

// round 6
// speedup vs baseline: 2.7298x; 1.2478x over previous
#include <cuda_runtime.h>
#include <cuda_fp16.h>
#include <math.h>
#include <stdint.h>

#define MM   16384
#define DD   512
#define FF   2048
#define NITER 11
#define THRESH (1.0f - 0.01f)

// SMEM tile geometry (fp16): 128 rows x (32 data + 8 pad) halves = 80B pitch
#define AP       40                      // halves per row
#define TILE_HB  (128 * AP * 2)          // 10240 B per matrix
#define STAGE_B  (4 * TILE_HB)           // Ah, Al, Bh, Bl = 40960 B
#define NSTAGE   2
#define DYN_SMEM (NSTAGE * STAGE_B)      // 81920 B -> 2 CTAs/SM

// Device scratch
__device__ float  g_st[(size_t)MM * DD];       // fp32 carried state
__device__ __half g_s_hi[(size_t)MM * DD];     // compact split s
__device__ __half g_s_lo[(size_t)MM * DD];
__device__ __half g_h_hi[(size_t)MM * FF];     // compact split hidden
__device__ __half g_h_lo[(size_t)MM * FF];
__device__ __half g_w1_hi[(size_t)FF * DD];    // W1^T [F][D]
__device__ __half g_w1_lo[(size_t)FF * DD];
__device__ __half g_w2_hi[(size_t)DD * FF];    // W2^T [D][F]
__device__ __half g_w2_lo[(size_t)DD * FF];
__device__ float  g_hp[MM];
__device__ float  g_uw[MM];
__device__ int    g_idx[MM];
__device__ int    g_nact[NITER + 1];
__device__ int    g_flag[NITER + 1];

// ---------------------------------------------------------------------------
__device__ __forceinline__ void cp_async16_s(uint32_t dst, const void* src) {
    asm volatile("cp.async.cg.shared.global [%0], [%1], 16;\n" :: "r"(dst), "l"(src));
}
template<int N> __device__ __forceinline__ void cp_wait() {
    asm volatile("cp.async.wait_group %0;\n" :: "n"(N) : "memory");
}

__device__ __forceinline__ void f16_split(float v, __half& hi, __half& lo) {
    hi = __float2half_rn(v);
    lo = __float2half_rn(v - __half2float(hi));
}

__device__ __forceinline__ void ldsm_x4(uint32_t& r0, uint32_t& r1,
                                        uint32_t& r2, uint32_t& r3, uint32_t a) {
    asm volatile("ldmatrix.sync.aligned.m8n8.x4.shared.b16 {%0,%1,%2,%3}, [%4];"
                 : "=r"(r0), "=r"(r1), "=r"(r2), "=r"(r3) : "r"(a));
}

__device__ __forceinline__ void mma_f16(float4& d,
    uint32_t a0, uint32_t a1, uint32_t a2, uint32_t a3,
    uint32_t b0, uint32_t b1) {
    asm volatile(
        "mma.sync.aligned.m16n8k16.row.col.f32.f16.f16.f32 "
        "{%0,%1,%2,%3}, {%4,%5,%6,%7}, {%8,%9}, {%0,%1,%2,%3};"
        : "+f"(d.x), "+f"(d.y), "+f"(d.z), "+f"(d.w)
        : "r"(a0), "r"(a1), "r"(a2), "r"(a3), "r"(b0), "r"(b1));
}

// ---------------------------------------------------------------------------
__global__ void init_kernel(const float* __restrict__ state, float* __restrict__ out)
{
    size_t i = (size_t)blockIdx.x * blockDim.x + threadIdx.x;
    if (i < (size_t)MM * DD) {
        g_st[i] = state[i];
        out[i]  = 0.0f;
    }
    if (i < MM) {
        g_hp[i] = 0.0f;
        out[(size_t)MM * DD + i] = 0.0f;
        out[(size_t)MM * DD + MM + i] = 0.0f;
    }
    if (i <= NITER) { g_flag[i] = (i == 0) ? 1 : 0; g_nact[i] = 0; }
}

// Transpose + split weights: W[K][N] -> Th/Tl [N][K] fp16
__global__ void wsplit_kernel(const float* __restrict__ W,
                              __half* __restrict__ Th, __half* __restrict__ Tl,
                              int K, int N)
{
    int i = blockIdx.x * blockDim.x + threadIdx.x;
    if (i >= K * N) return;
    int n = i / K, k = i - n * K;
    __half hi, lo;
    f16_split(W[(size_t)k * N + n], hi, lo);
    Th[i] = hi; Tl[i] = lo;
}

// ---------------------------------------------------------------------------
// Fused ponder + prep: one warp per row. Computes dot, halting state machine,
// compact index, and writes fp16-split s from registers (no re-read of g_st).
// Halting math bit-identical to prior passing rounds.
// ---------------------------------------------------------------------------
__global__ void ponder_kernel(const float* __restrict__ step_emb,
                              const float* __restrict__ Wp,
                              const float* __restrict__ bp,
                              float* __restrict__ out_nup,
                              float* __restrict__ out_rem,
                              int t)
{
    if (!g_flag[t]) return;
    int row  = blockIdx.x * 8 + (threadIdx.x >> 5);
    int lane = threadIdx.x & 31;

    __shared__ int s_active;
    if (threadIdx.x == 0) s_active = 0;
    __syncthreads();

    float hp = g_hp[row];
    if (hp < 1.0f) {
        const float4* st4 = (const float4*)(g_st + (size_t)row * DD);
        const float4* e4  = (const float4*)(step_emb + (size_t)t * DD);
        const float4* w4  = (const float4*)Wp;

        float4 sv[4];
        float dot = 0.0f;
        #pragma unroll
        for (int j = 0; j < 4; ++j) {
            int i = lane + j * 32;
            float4 s = st4[i], e = e4[i], w = w4[i];
            sv[j].x = s.x + e.x; sv[j].y = s.y + e.y;
            sv[j].z = s.z + e.z; sv[j].w = s.w + e.w;
            dot += sv[j].x * w.x + sv[j].y * w.y
                 + sv[j].z * w.z + sv[j].w * w.w;
        }
        #pragma unroll
        for (int o = 16; o; o >>= 1) dot += __shfl_xor_sync(0xffffffffu, dot, o);

        int pos = 0;
        if (lane == 0) {
            float p = 1.0f / (1.0f + expf(-(dot + bp[0])));
            float q  = hp + p;
            float nh = (q >  THRESH) ? 1.0f : 0.0f;
            float st = (q <= THRESH) ? 1.0f : 0.0f;
            hp = hp + p * st;
            float rem = out_rem[row] + nh * (1.0f - hp);
            hp = hp + nh * rem;
            out_nup[row] += 1.0f;
            g_hp[row]    = hp;
            out_rem[row] = rem;
            g_uw[row]    = p * st + nh * rem;
            pos = atomicAdd(&g_nact[t], 1);
            g_idx[pos] = row;
            if (hp < 1.0f) atomicOr(&s_active, 1);
        }
        pos = __shfl_sync(0xffffffffu, pos, 0);

        // Write fp16 split of s straight from registers into compact slot
        __half2* ph = (__half2*)(g_s_hi + (size_t)pos * DD);
        __half2* pl = (__half2*)(g_s_lo + (size_t)pos * DD);
        #pragma unroll
        for (int j = 0; j < 4; ++j) {
            int c2 = (lane + j * 32) * 2;      // half2 index
            __half h0, l0, h1, l1, h2, l2, h3, l3;
            f16_split(sv[j].x, h0, l0);
            f16_split(sv[j].y, h1, l1);
            f16_split(sv[j].z, h2, l2);
            f16_split(sv[j].w, h3, l3);
            ph[c2]     = __halves2half2(h0, h1);
            ph[c2 + 1] = __halves2half2(h2, h3);
            pl[c2]     = __halves2half2(l0, l1);
            pl[c2 + 1] = __halves2half2(l2, l3);
        }
    }
    __syncthreads();
    if (threadIdx.x == 0 && s_active) atomicOr(&g_flag[t + 1], 1);
}

// ---------------------------------------------------------------------------
// HMMA fp16-split GEMM: 128x128 CTA, BK=32, 2-stage cp.async, 2 CTAs/SM.
// MODE 0: g_h = relu(g_s @ W1' + b1)  (fp16-split output)
// MODE 1: h = g_h @ W2' + b2 (masked); out_prev[row]+=h*uw; g_st[row]=h
// ---------------------------------------------------------------------------
template<int KDIM, int NDIM, int MODE>
__global__ __launch_bounds__(256, 2) void gemm_hmma(
    const float* __restrict__ bias,
    const float* __restrict__ mask,
    float* __restrict__ out_prev, int t)
{
    const int nact = g_nact[t];
    const int bm = blockIdx.y * 128;
    if (bm >= nact) return;
    const int bn = blockIdx.x * 128;

    extern __shared__ unsigned char smem_raw[];
    uint32_t sb;
    asm("{ .reg .u64 tt; cvta.to.shared.u64 tt, %1; cvt.u32.u64 %0, tt; }"
        : "=r"(sb) : "l"(smem_raw));

    const int tid = threadIdx.x;

    // ---- global source pointers per loader tile (Ah, Al, Bh, Bl) ----
    const __half* Ahg = ((MODE == 0) ? g_s_hi : g_h_hi) + (size_t)bm * KDIM;
    const __half* Alg = ((MODE == 0) ? g_s_lo : g_h_lo) + (size_t)bm * KDIM;
    const __half* Bhg = ((MODE == 0) ? g_w1_hi : g_w2_hi) + (size_t)bn * KDIM;
    const __half* Blg = ((MODE == 0) ? g_w1_lo : g_w2_lo) + (size_t)bn * KDIM;
    const int tl = tid >> 6;
    const __half* tp = (tl == 0) ? Ahg : (tl == 1) ? Alg : (tl == 2) ? Bhg : Blg;
    const int u = tid & 63;
    const uint32_t tile_off = (uint32_t)tl * TILE_HB;

    #define LOAD_STAGE(slot, k0)                                               \
        do {                                                                   \
            uint32_t dst_ = sb + (uint32_t)(slot) * STAGE_B + tile_off;        \
            _Pragma("unroll")                                                  \
            for (int j_ = 0; j_ < 8; ++j_) {                                   \
                int ch_ = u + j_ * 64;                                         \
                int row_ = ch_ >> 2, c_ = ch_ & 3;                             \
                cp_async16_s(dst_ + (uint32_t)(row_ * (AP * 2) + c_ * 16),     \
                             tp + (size_t)row_ * KDIM + (k0) + c_ * 8);        \
            }                                                                  \
            asm volatile("cp.async.commit_group;" ::: "memory");               \
        } while (0)

    constexpr int KT = KDIM / 32;
    LOAD_STAGE(0, 0);
    cp_wait<0>();
    __syncthreads();

    // ---- warp tiling: 8 warps, 64x32 each ----
    const int lane = tid & 31;
    const int w    = tid >> 5;
    const int wm   = (w >> 2) * 64;
    const int wn   = (w & 3) * 32;
    const int lr   = lane & 15;
    const int lc   = (lane >> 4) * 8;

    float4 acc[4][4];
    #pragma unroll
    for (int i = 0; i < 4; ++i)
        #pragma unroll
        for (int j = 0; j < 4; ++j)
            acc[i][j] = make_float4(0.f, 0.f, 0.f, 0.f);

    #pragma unroll 1
    for (int kt = 0; kt < KT; ++kt) {
        if (kt + 1 < KT) LOAD_STAGE((kt + 1) & 1, (kt + 1) * 32);
        const uint32_t stg = sb + (uint32_t)(kt & 1) * STAGE_B;

        #pragma unroll
        for (int sub = 0; sub < 2; ++sub) {
            const int k0 = sub * 16;
            uint32_t bh[4][2], bl[4][2];
            #pragma unroll
            for (int njp = 0; njp < 2; ++njp) {
                uint32_t addr = stg + 2 * TILE_HB
                    + (uint32_t)(((wn + njp * 16 + lr) * AP + k0 + lc) * 2);
                uint32_t r0, r1, r2, r3;
                ldsm_x4(r0, r1, r2, r3, addr);
                bh[njp * 2][0] = r0; bh[njp * 2][1] = r2;
                bh[njp * 2 + 1][0] = r1; bh[njp * 2 + 1][1] = r3;
                addr += TILE_HB;
                ldsm_x4(r0, r1, r2, r3, addr);
                bl[njp * 2][0] = r0; bl[njp * 2][1] = r2;
                bl[njp * 2 + 1][0] = r1; bl[njp * 2 + 1][1] = r3;
            }
            #pragma unroll
            for (int mi = 0; mi < 4; ++mi) {
                uint32_t addr = stg
                    + (uint32_t)(((wm + mi * 16 + lr) * AP + k0 + lc) * 2);
                uint32_t ah0, ah1, ah2, ah3, al0, al1, al2, al3;
                ldsm_x4(ah0, ah1, ah2, ah3, addr);
                ldsm_x4(al0, al1, al2, al3, addr + TILE_HB);
                #pragma unroll
                for (int nj = 0; nj < 4; ++nj) {
                    mma_f16(acc[mi][nj], ah0, ah1, ah2, ah3, bh[nj][0], bh[nj][1]);
                    mma_f16(acc[mi][nj], ah0, ah1, ah2, ah3, bl[nj][0], bl[nj][1]);
                    mma_f16(acc[mi][nj], al0, al1, al2, al3, bh[nj][0], bh[nj][1]);
                }
            }
        }

        if (kt + 1 < KT) {
            cp_wait<0>();
            __syncthreads();
        }
    }
    #undef LOAD_STAGE

    // ---- epilogue ----
    const int g = lane >> 2;
    const int q = lane & 3;
    #pragma unroll
    for (int mi = 0; mi < 4; ++mi) {
        #pragma unroll
        for (int half = 0; half < 2; ++half) {
            const int m = bm + wm + mi * 16 + g + half * 8;
            if (m >= nact) continue;
            if (MODE == 0) {
                #pragma unroll
                for (int nj = 0; nj < 4; ++nj) {
                    const int col = bn + wn + nj * 8 + 2 * q;
                    float v0 = half ? acc[mi][nj].z : acc[mi][nj].x;
                    float v1 = half ? acc[mi][nj].w : acc[mi][nj].y;
                    v0 = fmaxf(v0 + bias[col], 0.0f);
                    v1 = fmaxf(v1 + bias[col + 1], 0.0f);
                    __half h0, l0, h1, l1;
                    f16_split(v0, h0, l0);
                    f16_split(v1, h1, l1);
                    *(__half2*)(g_h_hi + (size_t)m * NDIM + col) = __halves2half2(h0, h1);
                    *(__half2*)(g_h_lo + (size_t)m * NDIM + col) = __halves2half2(l0, l1);
                }
            } else {
                const int row = g_idx[m];
                const float mk  = mask[row];
                const float uwv = g_uw[row];
                #pragma unroll
                for (int nj = 0; nj < 4; ++nj) {
                    const int col = bn + wn + nj * 8 + 2 * q;
                    float v0 = half ? acc[mi][nj].z : acc[mi][nj].x;
                    float v1 = half ? acc[mi][nj].w : acc[mi][nj].y;
                    float h0 = (v0 + bias[col])     * mk;
                    float h1 = (v1 + bias[col + 1]) * mk;
                    float* pp = out_prev + (size_t)row * NDIM + col;
                    float* sp = g_st     + (size_t)row * NDIM + col;
                    float2 pv = *(const float2*)pp;
                    pv.x += h0 * uwv;
                    pv.y += h1 * uwv;
                    *(float2*)pp = pv;
                    *(float2*)sp = make_float2(h0, h1);
                }
            }
        }
    }
}

// ---------------------------------------------------------------------------
extern "C" void kernel_launch(void* const* d_in, const int* in_sizes, int n_in,
                              void* d_out, int out_size)
{
    const float* state    = (const float*)d_in[0];
    const float* mask     = (const float*)d_in[1];
    const float* step_emb = (const float*)d_in[2];
    const float* Wp       = (const float*)d_in[3];
    const float* bp       = (const float*)d_in[4];
    const float* W1       = (const float*)d_in[5];
    const float* b1       = (const float*)d_in[6];
    const float* W2       = (const float*)d_in[7];
    const float* b2       = (const float*)d_in[8];

    float* out     = (float*)d_out;
    float* out_nup = out + (size_t)MM * DD;
    float* out_rem = out_nup + MM;

    cudaFuncSetAttribute(gemm_hmma<DD, FF, 0>,
        cudaFuncAttributeMaxDynamicSharedMemorySize, DYN_SMEM);
    cudaFuncSetAttribute(gemm_hmma<FF, DD, 1>,
        cudaFuncAttributeMaxDynamicSharedMemorySize, DYN_SMEM);

    init_kernel<<<(MM * DD + 255) / 256, 256>>>(state, out);

    {
        __half *w1h, *w1l, *w2h, *w2l;
        cudaGetSymbolAddress((void**)&w1h, g_w1_hi);
        cudaGetSymbolAddress((void**)&w1l, g_w1_lo);
        cudaGetSymbolAddress((void**)&w2h, g_w2_hi);
        cudaGetSymbolAddress((void**)&w2l, g_w2_lo);
        wsplit_kernel<<<(DD * FF + 255) / 256, 256>>>(W1, w1h, w1l, DD, FF);
        wsplit_kernel<<<(FF * DD + 255) / 256, 256>>>(W2, w2h, w2l, FF, DD);
    }

    dim3 g1(FF / 128, MM / 128);   // (16, 128)
    dim3 g2(DD / 128, MM / 128);   // (4, 128)

    for (int t = 0; t < NITER; ++t) {
        ponder_kernel<<<MM / 8, 256>>>(step_emb, Wp, bp, out_nup, out_rem, t);
        gemm_hmma<DD, FF, 0><<<g1, 256, DYN_SMEM>>>(b1, nullptr, nullptr, t);
        gemm_hmma<FF, DD, 1><<<g2, 256, DYN_SMEM>>>(b2, mask, out, t);
    }
}